// round 15
// baseline (speedup 1.0000x reference)
#include <cuda_runtime.h>
#include <cuda_fp16.h>
#include <math.h>
#include <cstdint>

#define M_TOTAL 81920
#define NGROUP  2048
#define NENT    14541
#define NRELS   237
#define NENT_P  14592
#define K_PAD   640
#define K_PAD2  128

// ---------------- scratch (device globals) ----------------------------------
__device__ __half g_Pe[3][NENT*400];        // fp16 gate tables
__device__ __half g_Pr[3][NRELS*400];
__device__ __half g_R1[3][NENT*400];
__device__ float  g_h1c1[3][NENT*200];
__device__ float  g_c2[(size_t)3*M_TOTAL*100];
__device__ __align__(16) __half g_R2f[(size_t)3*M_TOTAL*400];
__device__ float  g_out[(size_t)M_TOTAL*600];
__device__ __align__(16) __half g_hGf[(size_t)M_TOTAL*600];
__device__ float  g_op [(size_t)M_TOTAL*100];
// fp16 GEMM operands (pads stay zero)
__device__ __align__(16) __half g_Af[(size_t)M_TOTAL*K_PAD];
__device__ __align__(16) __half g_BTf[640*K_PAD];
__device__ __align__(16) __half g_h2f[(size_t)3*M_TOTAL*K_PAD2];
__device__ __align__(16) __half g_Wf[6][512*K_PAD2];   // 0..2 Whh, 3..5 Wih
__device__ __align__(16) __half g_Ef[2][NENT_P*K_PAD2];
__device__ __align__(16) __half g_Rf2[2][256*K_PAD2];
__device__ __align__(16) __half g_h1f[3][NENT_P*K_PAD2];

// fast transcendentals: hardware MUFU.TANH (1 op) instead of exp+rcp (2 ops)
__device__ __forceinline__ float tanh_fast(float x){
    float y;
    asm("tanh.approx.f32 %0, %1;" : "=f"(y) : "f"(x));
    return y;
}
__device__ __forceinline__ float sigmoid_fast(float x){
    return fmaf(tanh_fast(0.5f*x), 0.5f, 0.5f);
}
__device__ __forceinline__ void storeh4(float4 v, __half* p){
    ((__half2*)p)[0] = __floats2half2_rn(v.x, v.y);
    ((__half2*)p)[1] = __floats2half2_rn(v.z, v.w);
}
__device__ __forceinline__ float4 loadh4(const __half* p){
    __half2 a = ((const __half2*)p)[0], b = ((const __half2*)p)[1];
    float2 fa=__half22float2(a), fb=__half22float2(b);
    return make_float4(fa.x,fa.y,fb.x,fb.y);
}

// ======================= MMA plumbing =======================================
__device__ __forceinline__ void cp16(unsigned saddr, const void* g){
    asm volatile("cp.async.cg.shared.global [%0], [%1], 16;" :: "r"(saddr), "l"(g));
}
__device__ __forceinline__ void cp_commit(){
    asm volatile("cp.async.commit_group;" ::: "memory");
}
template<int N> __device__ __forceinline__ void cp_wait(){
    asm volatile("cp.async.wait_group %0;" :: "n"(N) : "memory");
}
__device__ __forceinline__ void ldm4(uint32_t* r, unsigned addr){
    asm volatile("ldmatrix.sync.aligned.m8n8.x4.shared.b16 {%0,%1,%2,%3}, [%4];"
        : "=r"(r[0]), "=r"(r[1]), "=r"(r[2]), "=r"(r[3]) : "r"(addr));
}
__device__ __forceinline__ void mma16816h(float* d, const uint32_t* a, uint32_t b0, uint32_t b1){
    asm volatile("mma.sync.aligned.m16n8k16.row.col.f32.f16.f16.f32 "
        "{%0,%1,%2,%3},{%4,%5,%6,%7},{%8,%9},{%0,%1,%2,%3};"
        : "+f"(d[0]), "+f"(d[1]), "+f"(d[2]), "+f"(d[3])
        : "r"(a[0]), "r"(a[1]), "r"(a[2]), "r"(a[3]), "r"(b0), "r"(b1));
}

// ======================= fp16 single-pass GEMM ==============================
#define STG_F16 24576
#define MMF_SMEM (2*STG_F16)

__device__ __forceinline__ void stageF(unsigned sb,
    const __half* A, size_t lda, int mrow0, int Mv,
    const __half* B, size_t ldb, int kcol, int tid)
{
    for (int i=tid;i<512;i+=256){
        int r=i>>3, c=i&7;
        unsigned off = (unsigned)((r*128 + c*16) ^ ((r&7)<<4));
        int ra = mrow0 + r; if (ra >= Mv) ra = Mv-1;
        cp16(sb + off, A + (size_t)ra*lda + kcol + c*8);
    }
    for (int i=tid;i<1024;i+=256){
        int r=i>>3, c=i&7;
        unsigned off = (unsigned)((r*128 + c*16) ^ ((r&7)<<4));
        cp16(sb + 8192 + off, B + (size_t)r*ldb + kcol + c*8);
    }
}

__global__ void __launch_bounds__(256,3) mma_f16(int which)
{
    extern __shared__ char smraw[];
    unsigned sbase;
    asm("{ .reg .u64 t; cvta.to.shared.u64 t, %1; cvt.u32.u64 %0, t; }" : "=r"(sbase) : "l"(smraw));
    int tid=threadIdx.x, wid=tid>>5, lane=tid&31;
    int wm = wid & 1, wn = wid >> 1;
    int ncol0 = blockIdx.x*128, mrow0 = blockIdx.y*64;
    int z = blockIdx.z;

    const __half *A, *B; __half* C; int Nv, ldc, nch, Mv; size_t lda, ldb;
    switch (which){
      case 0:
        A = g_Af; B = g_BTf + (size_t)ncol0*K_PAD;
        C = g_hGf; Nv=600; ldc=600; nch=10; lda=K_PAD; ldb=K_PAD; Mv=M_TOTAL; break;
      case 1:
        A = g_h2f + (size_t)z*M_TOTAL*K_PAD2;
        B = g_Wf[z] + (size_t)ncol0*K_PAD2;
        C = g_R2f + (size_t)z*M_TOTAL*400;
        Nv=400; ldc=400; nch=2; lda=K_PAD2; ldb=K_PAD2; Mv=M_TOTAL; break;
      case 2: {
        int e = (z==2)? 1 : 0;
        A = g_Ef[e]; B = g_Wf[3+z] + (size_t)ncol0*K_PAD2; C = g_Pe[z];
        Nv=400; ldc=400; nch=2; lda=K_PAD2; ldb=K_PAD2; Mv=NENT; break; }
      case 3: {
        int e = (z==2)? 1 : 0;
        A = g_Rf2[e]; B = g_Wf[3+z] + (size_t)ncol0*K_PAD2; C = g_Pr[z];
        Nv=400; ldc=400; nch=2; lda=K_PAD2; ldb=K_PAD2; Mv=NRELS; break; }
      default:
        A = g_h1f[z]; B = g_Wf[z] + (size_t)ncol0*K_PAD2; C = g_R1[z];
        Nv=400; ldc=400; nch=2; lda=K_PAD2; ldb=K_PAD2; Mv=NENT; break;
    }

    float acc[2][4][4];
    #pragma unroll
    for (int i=0;i<2;i++)
        #pragma unroll
        for (int j=0;j<4;j++)
            #pragma unroll
            for (int q=0;q<4;q++) acc[i][j][q]=0.f;

    stageF(sbase,           A,lda,mrow0,Mv, B,ldb, 0,  tid); cp_commit();
    stageF(sbase + STG_F16, A,lda,mrow0,Mv, B,ldb, 64, tid); cp_commit();

    int lr  = lane & 15;
    int lhb = (lane >> 4) << 4;

    for (int k=0;k<nch;k++){
        if (k < nch-1) cp_wait<1>(); else cp_wait<0>();
        __syncthreads();
        unsigned st = sbase + (unsigned)(k&1)*STG_F16;
        unsigned sA = st, sB = st+8192;
        #pragma unroll
        for (int kk=0;kk<4;kk++){
            int cb = kk*32 + lhb;
            uint32_t ah[2][4], bb[2][4];
            #pragma unroll
            for (int mt=0;mt<2;mt++){
                int r = wm*32 + mt*16 + lr;
                unsigned off = (unsigned)((r*128 + cb) ^ ((r&7)<<4));
                ldm4(ah[mt], sA + off);
            }
            #pragma unroll
            for (int ng=0;ng<2;ng++){
                int n = wn*32 + ng*16 + lr;
                unsigned off = (unsigned)((n*128 + cb) ^ ((n&7)<<4));
                ldm4(bb[ng], sB + off);
            }
            #pragma unroll
            for (int mt=0;mt<2;mt++){
                #pragma unroll
                for (int nt=0;nt<4;nt++){
                    int ng = nt>>1, s = nt&1;
                    mma16816h(acc[mt][nt], ah[mt], bb[ng][s], bb[ng][s+2]);
                }
            }
        }
        __syncthreads();
        if (k+2 < nch){
            stageF(st, A,lda,mrow0,Mv, B,ldb, (k+2)*64, tid);
            cp_commit();
        }
    }
    #pragma unroll
    for (int mt=0;mt<2;mt++){
        int rbase = mrow0 + wm*32 + mt*16 + (lane>>2);
        #pragma unroll
        for (int nt=0;nt<4;nt++){
            int col = ncol0 + wn*32 + nt*8 + (lane&3)*2;
            if (col < Nv){
                if (rbase < Mv)
                    *(__half2*)(C + (size_t)rbase*ldc + col)     = __floats2half2_rn(acc[mt][nt][0], acc[mt][nt][1]);
                if (rbase+8 < Mv)
                    *(__half2*)(C + (size_t)(rbase+8)*ldc + col) = __floats2half2_rn(acc[mt][nt][2], acc[mt][nt][3]);
            }
        }
    }
}

// ---------------------------------------------------------------------------
// conversions
// ---------------------------------------------------------------------------
__global__ void convB_kernel(const float* __restrict__ W1)
{
    int i = blockIdx.x*256 + threadIdx.x;
    if (i >= 600*600) return;
    int n = i / 600, k = i - n*600;
    g_BTf[(size_t)n*K_PAD + k] = __float2half(W1[(size_t)k*600 + n]);
}
__global__ void convW6_kernel(const float* __restrict__ Whf, const float* __restrict__ Whb,
                              const float* __restrict__ Whp, const float* __restrict__ Wif,
                              const float* __restrict__ Wib, const float* __restrict__ Wip)
{
    int i = blockIdx.x*256 + threadIdx.x;
    if (i >= 6*400*100) return;
    int m = i / 40000; int rem = i - m*40000;
    int n = rem/100, k = rem - n*100;
    const float* W;
    switch(m){ case 0:W=Whf;break; case 1:W=Whb;break; case 2:W=Whp;break;
               case 3:W=Wif;break; case 4:W=Wib;break; default:W=Wip;break; }
    g_Wf[m][n*K_PAD2 + k] = __float2half(W[n*100+k]);
}
__global__ void convE_kernel(const float* __restrict__ ent, const float* __restrict__ ent1,
                             const float* __restrict__ rel, const float* __restrict__ rel1)
{
    int i = blockIdx.x*256 + threadIdx.x;
    if (i < 2*NENT*100){
        int e = i / (NENT*100); int rem = i - e*(NENT*100);
        int r = rem/100, k = rem - r*100;
        const float* src = e ? ent1 : ent;
        g_Ef[e][(size_t)r*K_PAD2+k] = __float2half(src[(size_t)r*100+k]);
    } else {
        int j = i - 2*NENT*100;
        if (j >= 2*NRELS*100) return;
        int e = j / (NRELS*100); int rem = j - e*(NRELS*100);
        int r = rem/100, k = rem - r*100;
        const float* src = e ? rel1 : rel;
        g_Rf2[e][(size_t)r*K_PAD2+k] = __float2half(src[(size_t)r*100+k]);
    }
}

// ---------------------------------------------------------------------------
__global__ void step1_kernel(const float* __restrict__ b_f,
                             const float* __restrict__ b_b,
                             const float* __restrict__ b_p)
{
    int idx = blockIdx.x*256 + threadIdx.x;
    if (idx >= 3*NENT*100) return;
    int l   = idx / (NENT*100);
    int rem = idx - l*(NENT*100);
    int e = rem/100, j = rem - e*100;
    const __half* P = g_Pe[l] + (size_t)e*400;
    const float* b = (l==0)? b_f : (l==1)? b_b : b_p;
    float iv = __half2float(P[j])     + b[j];
    float gv = __half2float(P[200+j]) + b[200+j];
    float ov = __half2float(P[300+j]) + b[300+j];
    float c1 = sigmoid_fast(iv) * tanh_fast(gv);
    float h1 = sigmoid_fast(ov) * tanh_fast(c1);
    g_h1c1[l][(size_t)e*200 + j]       = h1;
    g_h1c1[l][(size_t)e*200 + 100 + j] = c1;
    g_h1f[l][(size_t)e*K_PAD2 + j] = __float2half(h1);
}

// ---------------------------------------------------------------------------
// step12: one layer per blockIdx.y
// ---------------------------------------------------------------------------
__global__ void __launch_bounds__(256) step12_kernel(
    const int* __restrict__ bh, const int* __restrict__ br, const int* __restrict__ bt,
    const float* __restrict__ b_f, const float* __restrict__ b_b, const float* __restrict__ b_p)
{
    __shared__ int ifr[64], ir[64];
    int tid=threadIdx.x; int row0=blockIdx.x*64;
    int l = blockIdx.y;
    if (tid<64)        ifr[tid]    = (l==1)? bt[row0+tid] : bh[row0+tid];
    else if (tid<128)  ir[tid-64]  = br[row0+tid-64];
    __syncthreads();
    const __half* Pr = g_Pr[l];
    const __half* R1 = g_R1[l];
    const float*  HC = g_h1c1[l];
    const float* bias= (l==0)?b_f:(l==1)?b_b:b_p;
    for (int t=tid;t<1600;t+=256){
        int row=t/25, q=t-row*25; int j=q*4;
        int fi = ifr[row];
        size_t grow=(size_t)(row0+row);
        bool emit_out = ((grow % 80u)==0u) && (l<2);
        float4 h1v = *(const float4*)&HC[(size_t)fi*200 + j];
        float4 c1v = *(const float4*)&HC[(size_t)fi*200 + 100 + j];
        if (l==0){
            if (emit_out) *(float4*)&g_out[grow*600 + j] = h1v;
            storeh4(h1v, &g_Af[grow*K_PAD + j]);
        } else if (l==1){
            if (emit_out) *(float4*)&g_out[grow*600 + 500 + j] = h1v;
            storeh4(h1v, &g_Af[grow*K_PAD + 500 + j]);
        }
        const __half* pr = Pr + (size_t)ir[row]*400;
        const __half* r1 = R1 + (size_t)fi*400;
        float4 pi = loadh4(pr+j),      riv = loadh4(r1+j);
        float4 pf = loadh4(pr+100+j),  rf  = loadh4(r1+100+j);
        float4 pg = loadh4(pr+200+j),  rg  = loadh4(r1+200+j);
        float4 po = loadh4(pr+300+j),  ro  = loadh4(r1+300+j);
        float4 bi = *(const float4*)&bias[j],    bf4= *(const float4*)&bias[100+j];
        float4 bg = *(const float4*)&bias[200+j],bo = *(const float4*)&bias[300+j];
        float4 c2v, h2v;
        {
            float c,h;
            c = sigmoid_fast(pf.x+rf.x+bf4.x)*c1v.x + sigmoid_fast(pi.x+riv.x+bi.x)*tanh_fast(pg.x+rg.x+bg.x);
            h = sigmoid_fast(po.x+ro.x+bo.x)*tanh_fast(c); c2v.x=c; h2v.x=h;
            c = sigmoid_fast(pf.y+rf.y+bf4.y)*c1v.y + sigmoid_fast(pi.y+riv.y+bi.y)*tanh_fast(pg.y+rg.y+bg.y);
            h = sigmoid_fast(po.y+ro.y+bo.y)*tanh_fast(c); c2v.y=c; h2v.y=h;
            c = sigmoid_fast(pf.z+rf.z+bf4.z)*c1v.z + sigmoid_fast(pi.z+riv.z+bi.z)*tanh_fast(pg.z+rg.z+bg.z);
            h = sigmoid_fast(po.z+ro.z+bo.z)*tanh_fast(c); c2v.z=c; h2v.z=h;
            c = sigmoid_fast(pf.w+rf.w+bf4.w)*c1v.w + sigmoid_fast(pi.w+riv.w+bi.w)*tanh_fast(pg.w+rg.w+bg.w);
            h = sigmoid_fast(po.w+ro.w+bo.w)*tanh_fast(c); c2v.w=c; h2v.w=h;
        }
        storeh4(h2v, &g_h2f[(size_t)l*M_TOTAL*K_PAD2 + grow*K_PAD2 + j]);
        *(float4*)&g_c2[(size_t)l*M_TOTAL*100 + grow*100 + j] = c2v;
        if (l==0){
            if (emit_out) *(float4*)&g_out[grow*600 + 200 + j] = h2v;
            storeh4(h2v, &g_Af[grow*K_PAD + 200 + j]);
        } else if (l==1){
            if (emit_out) *(float4*)&g_out[grow*600 + 300 + j] = h2v;
            storeh4(h2v, &g_Af[grow*K_PAD + 300 + j]);
        }
    }
}

// ---------------------------------------------------------------------------
// step3: one layer per blockIdx.y
// ---------------------------------------------------------------------------
__global__ void __launch_bounds__(256) step3_kernel(
    const int* __restrict__ bh, const int* __restrict__ bt,
    const float* __restrict__ b_f, const float* __restrict__ b_b, const float* __restrict__ b_p)
{
    __shared__ int ila[64];
    int tid=threadIdx.x; int row0=blockIdx.x*64;
    int l = blockIdx.y;
    if (tid<64) ila[tid] = (l==1)? bh[row0+tid] : bt[row0+tid];
    __syncthreads();
    const __half* Pe = g_Pe[l];
    const __half* R2 = g_R2f + (size_t)l*M_TOTAL*400;
    const float*  C2 = g_c2 + (size_t)l*M_TOTAL*100;
    const float* bias= (l==0)?b_f:(l==1)?b_b:b_p;
    for (int t=tid;t<1600;t+=256){
        int row=t/25, q=t-row*25; int j=q*4;
        int li = ila[row];
        size_t grow=(size_t)(row0+row);
        const __half* pe = Pe + (size_t)li*400;
        const __half* r2 = R2 + grow*400;
        float4 pi = loadh4(pe+j),      riv = loadh4(r2+j);
        float4 pf = loadh4(pe+100+j),  rf  = loadh4(r2+100+j);
        float4 pg = loadh4(pe+200+j),  rg  = loadh4(r2+200+j);
        float4 po = loadh4(pe+300+j),  ro  = loadh4(r2+300+j);
        float4 bi = *(const float4*)&bias[j],    bf4= *(const float4*)&bias[100+j];
        float4 bg = *(const float4*)&bias[200+j],bo = *(const float4*)&bias[300+j];
        float4 c2v = *(const float4*)&C2[grow*100 + j];
        float4 h3v;
        {
            float c;
            c = sigmoid_fast(pf.x+rf.x+bf4.x)*c2v.x + sigmoid_fast(pi.x+riv.x+bi.x)*tanh_fast(pg.x+rg.x+bg.x);
            h3v.x = sigmoid_fast(po.x+ro.x+bo.x)*tanh_fast(c);
            c = sigmoid_fast(pf.y+rf.y+bf4.y)*c2v.y + sigmoid_fast(pi.y+riv.y+bi.y)*tanh_fast(pg.y+rg.y+bg.y);
            h3v.y = sigmoid_fast(po.y+ro.y+bo.y)*tanh_fast(c);
            c = sigmoid_fast(pf.z+rf.z+bf4.z)*c2v.z + sigmoid_fast(pi.z+riv.z+bi.z)*tanh_fast(pg.z+rg.z+bg.z);
            h3v.z = sigmoid_fast(po.z+ro.z+bo.z)*tanh_fast(c);
            c = sigmoid_fast(pf.w+rf.w+bf4.w)*c2v.w + sigmoid_fast(pi.w+riv.w+bi.w)*tanh_fast(pg.w+rg.w+bg.w);
            h3v.w = sigmoid_fast(po.w+ro.w+bo.w)*tanh_fast(c);
        }
        bool emit_out = ((grow % 80u)==0u);
        if (l==0){
            if (emit_out) *(float4*)&g_out[grow*600 + 400 + j] = h3v;
            storeh4(h3v, &g_Af[grow*K_PAD + 400 + j]);
        } else if (l==1){
            if (emit_out) *(float4*)&g_out[grow*600 + 100 + j] = h3v;
            storeh4(h3v, &g_Af[grow*K_PAD + 100 + j]);
        } else {
            *(float4*)&g_op[grow*100 + j] = h3v;
        }
    }
}

// ---------------------------------------------------------------------------
// GAT1 attention (streaming form)
// ---------------------------------------------------------------------------
__global__ void __launch_bounds__(256,1) gat1_att(
    const float* __restrict__ a1, float* __restrict__ out_att, float* __restrict__ out2)
{
    __shared__ __align__(16) float a1s[1200];
    __shared__ float ebuf[41];
    __shared__ float att[40];
    __shared__ float red[2];
    int b=blockIdx.x, tid=threadIdx.x, warp=tid>>5, lane=tid&31;
    for (int i=tid;i<1200;i+=256) a1s[i]=a1[i];
    __syncthreads();
    const __half* base = g_hGf + (size_t)b*24000;
    for (int t=warp;t<41;t+=8){
        const __half* rowp = (t<40)? base + t*600 : base;
        const float* av    = (t<40)? a1s          : a1s+600;
        float s=0.f;
        for (int kk=lane;kk<75;kk+=32){
            uint4 raw = *(const uint4*)(rowp + kk*8);
            __half2* hv = (__half2*)&raw;
            const float* ap = av + kk*8;
            float2 f0=__half22float2(hv[0]), f1=__half22float2(hv[1]);
            float2 f2=__half22float2(hv[2]), f3=__half22float2(hv[3]);
            s += f0.x*ap[0]+f0.y*ap[1]+f1.x*ap[2]+f1.y*ap[3]
               + f2.x*ap[4]+f2.y*ap[5]+f3.x*ap[6]+f3.y*ap[7];
        }
        #pragma unroll
        for (int o=16;o;o>>=1) s += __shfl_xor_sync(0xffffffffu, s, o);
        if (lane==0) ebuf[t]=s;
    }
    __syncthreads();
    if (tid<40){
        float x = ebuf[tid] + ebuf[40];
        ebuf[tid] = (x>0.f)? x : 0.2f*x;
    }
    __syncthreads();
    if (tid<32){
        float v = ebuf[tid];
        if (tid<8) v = fmaxf(v, ebuf[tid+32]);
        #pragma unroll
        for (int o=16;o;o>>=1) v = fmaxf(v, __shfl_xor_sync(0xffffffffu, v, o));
        if (tid==0) red[0]=v;
    }
    __syncthreads();
    if (tid<40) att[tid]=__expf(ebuf[tid]-red[0]);
    __syncthreads();
    if (tid<32){
        float v = att[tid] + ((tid<8)? att[tid+32] : 0.f);
        #pragma unroll
        for (int o=16;o;o>>=1) v += __shfl_xor_sync(0xffffffffu, v, o);
        if (tid==0) red[1]=1.f/v;
    }
    __syncthreads();
    if (tid<40) att[tid]=fmaxf(att[tid]*red[1]-0.001f, 0.f);
    __syncthreads();
    for (int f2=tid; f2<300; f2+=256){
        float ax=0.f, ay=0.f;
        const __half2* col = (const __half2*)base + f2;
        #pragma unroll 8
        for (int n=0;n<40;n++){
            float2 v = __half22float2(col[n*300]);
            ax += att[n]*v.x; ay += att[n]*v.y;
        }
        out_att[(size_t)b*600 + f2*2]     = ax;
        out_att[(size_t)b*600 + f2*2 + 1] = ay;
    }
    if ((b&1)==0){
        const float* srow = g_out + (size_t)b*40*600;
        float* drow = out2 + (size_t)(b>>1)*600;
        for (int f=tid;f<600;f+=256) drow[f]=srow[f];
    }
}

// ---------------------------------------------------------------------------
#define GAT2_SMEM ((4000 + 10000 + 4000)*4)
__global__ void __launch_bounds__(256,1) gat2_kernel(
    const float* __restrict__ W2, const float* __restrict__ a2,
    float* __restrict__ output_att, float* __restrict__ op2)
{
    extern __shared__ float sm[];
    float* ops = sm;
    float* Ws  = ops + 4000;
    float* hg  = Ws  + 10000;
    __shared__ float a2s[200];
    __shared__ float ebuf[41];
    __shared__ float att[40];
    __shared__ float red[2];
    int b=blockIdx.x, tid=threadIdx.x, warp=tid>>5, lane=tid&31;
    const float* src = g_op + (size_t)b*4000;
    for (int i=tid;i<4000;i+=256)  ops[i]=src[i];
    for (int i=tid;i<10000;i+=256) Ws[i]=W2[i];
    if (tid<200) a2s[tid]=a2[tid];
    __syncthreads();
    for (int i=tid;i<4000;i+=256){
        int n=i/100, o=i-n*100;
        float acc=0.f;
        #pragma unroll 4
        for (int k=0;k<100;k++) acc=fmaf(ops[n*100+k], Ws[k*100+o], acc);
        hg[i]=acc;
    }
    __syncthreads();
    for (int t=warp;t<41;t+=8){
        const float* rowp = (t<40)? hg + t*100 : hg;
        const float* av   = (t<40)? a2s        : a2s+100;
        float s=0.f;
        for (int k=lane;k<100;k+=32) s += rowp[k]*av[k];
        #pragma unroll
        for (int o=16;o;o>>=1) s += __shfl_xor_sync(0xffffffffu, s, o);
        if (lane==0) ebuf[t]=s;
    }
    __syncthreads();
    if (tid<40){
        float x = ebuf[tid] + ebuf[40];
        ebuf[tid] = (x>0.f)? x : 0.2f*x;
    }
    __syncthreads();
    if (tid<32){
        float v = ebuf[tid];
        if (tid<8) v = fmaxf(v, ebuf[tid+32]);
        #pragma unroll
        for (int o=16;o;o>>=1) v = fmaxf(v, __shfl_xor_sync(0xffffffffu, v, o));
        if (tid==0) red[0]=v;
    }
    __syncthreads();
    if (tid<40) att[tid]=__expf(ebuf[tid]-red[0]);
    __syncthreads();
    if (tid<32){
        float v = att[tid] + ((tid<8)? att[tid+32] : 0.f);
        #pragma unroll
        for (int o=16;o;o>>=1) v += __shfl_xor_sync(0xffffffffu, v, o);
        if (tid==0) red[1]=1.f/v;
    }
    __syncthreads();
    if (tid<40) att[tid]=fmaxf(att[tid]*red[1]-0.001f, 0.f);
    __syncthreads();
    if (tid<100){
        float acc=0.f;
        #pragma unroll 8
        for (int n=0;n<40;n++) acc += att[n]*hg[n*100+tid];
        output_att[(size_t)b*100+tid]=acc;
    }
    if ((b&1)==0){
        const float* srow = g_op + (size_t)b*40*100;
        float* drow = op2 + (size_t)(b>>1)*100;
        if (tid<100) drow[tid]=srow[tid];
    }
}

// ---------------------------------------------------------------------------
extern "C" void kernel_launch(void* const* d_in, const int* in_sizes, int n_in,
                              void* d_out, int out_size)
{
    const int*   bh    = (const int*)  d_in[0];
    const int*   br    = (const int*)  d_in[1];
    const int*   bt    = (const int*)  d_in[2];
    const float* ent   = (const float*)d_in[3];
    const float* rel   = (const float*)d_in[4];
    const float* ent1  = (const float*)d_in[5];
    const float* rel1  = (const float*)d_in[6];
    const float* Wih_f = (const float*)d_in[7];
    const float* Whh_f = (const float*)d_in[8];
    const float* b_f   = (const float*)d_in[9];
    const float* Wih_b = (const float*)d_in[10];
    const float* Whh_b = (const float*)d_in[11];
    const float* b_b   = (const float*)d_in[12];
    const float* Wih_p = (const float*)d_in[13];
    const float* Whh_p = (const float*)d_in[14];
    const float* b_p   = (const float*)d_in[15];
    const float* W1    = (const float*)d_in[16];
    const float* a1    = (const float*)d_in[17];
    const float* W2    = (const float*)d_in[18];
    const float* a2    = (const float*)d_in[19];

    float* out        = (float*)d_out;
    float* out2       = out;                          // [1024,600]
    float* out_att    = out + 1024*600;               // [2048,600]
    float* op2        = out + 1024*600 + 2048*600;    // [1024,100]
    float* output_att = op2 + 1024*100;               // [2048,100]

    cudaFuncSetAttribute(gat2_kernel, cudaFuncAttributeMaxDynamicSharedMemorySize, GAT2_SMEM);
    cudaFuncSetAttribute(mma_f16,     cudaFuncAttributeMaxDynamicSharedMemorySize, MMF_SMEM);

    convB_kernel<<<(600*600 + 255)/256, 256>>>(W1);
    convW6_kernel<<<(6*400*100 + 255)/256, 256>>>(Whh_f, Whh_b, Whh_p, Wih_f, Wih_b, Wih_p);
    convE_kernel<<<(2*(NENT+NRELS)*100 + 255)/256, 256>>>(ent, ent1, rel, rel1);

    dim3 pe(4, NENT_P/64, 3);
    mma_f16<<<pe, 256, MMF_SMEM>>>(2);
    dim3 pr(4, 4, 3);
    mma_f16<<<pr, 256, MMF_SMEM>>>(3);

    step1_kernel<<<(3*NENT*100 + 255)/256, 256>>>(b_f, b_b, b_p);

    mma_f16<<<pe, 256, MMF_SMEM>>>(4);

    dim3 sg(M_TOTAL/64, 3);
    step12_kernel<<<sg, 256>>>(bh, br, bt, b_f, b_b, b_p);

    dim3 rg(4, M_TOTAL/64, 3);
    mma_f16<<<rg, 256, MMF_SMEM>>>(1);

    step3_kernel<<<sg, 256>>>(bh, bt, b_f, b_b, b_p);

    dim3 gg(5, M_TOTAL/64, 1);
    mma_f16<<<gg, 256, MMF_SMEM>>>(0);

    gat1_att<<<NGROUP, 256>>>(a1, out_att, out2);

    gat2_kernel<<<NGROUP, 256, GAT2_SMEM>>>(W2, a2, output_att, op2);

    (void)in_sizes; (void)n_in; (void)out_size;
}

// round 16
// speedup vs baseline: 1.2869x; 1.2869x over previous
#include <cuda_runtime.h>
#include <cuda_fp16.h>
#include <math.h>
#include <cstdint>

#define M_TOTAL 81920
#define NGROUP  2048
#define NENT    14541
#define NRELS   237
#define NENT_P  14592
#define K_PAD   640
#define K_PAD2  128

// ---------------- scratch (device globals) ----------------------------------
__device__ __half g_Pe[3][NENT*400];        // fp16 gate tables
__device__ __half g_Pr[3][NRELS*400];
__device__ __half g_R1[3][NENT*400];
__device__ float  g_h1c1[3][NENT*200];
__device__ float  g_c2[(size_t)3*M_TOTAL*100];
__device__ __align__(16) __half g_R2f[(size_t)3*M_TOTAL*400];
__device__ float  g_out[(size_t)M_TOTAL*600];
__device__ float  g_op [(size_t)M_TOTAL*100];
// fp16 GEMM operands (pads stay zero)
__device__ __align__(16) __half g_Af[(size_t)M_TOTAL*K_PAD];
__device__ __align__(16) __half g_BTf[640*K_PAD];
__device__ __align__(16) __half g_h2f[(size_t)3*M_TOTAL*K_PAD2];
__device__ __align__(16) __half g_Wf[6][512*K_PAD2];   // 0..2 Whh, 3..5 Wih
__device__ __align__(16) __half g_Ef[2][NENT_P*K_PAD2];
__device__ __align__(16) __half g_Rf2[2][256*K_PAD2];
__device__ __align__(16) __half g_h1f[3][NENT_P*K_PAD2];
// GAT1 factored pieces
__device__ float g_v1[600];
__device__ float g_v2[600];
__device__ __align__(16) __half g_Sf[(size_t)NGROUP*K_PAD];  // pad cols stay zero

__device__ __forceinline__ float tanh_fast(float x){
    float y;
    asm("tanh.approx.f32 %0, %1;" : "=f"(y) : "f"(x));
    return y;
}
__device__ __forceinline__ float sigmoid_fast(float x){
    return fmaf(tanh_fast(0.5f*x), 0.5f, 0.5f);
}
__device__ __forceinline__ void storeh4(float4 v, __half* p){
    ((__half2*)p)[0] = __floats2half2_rn(v.x, v.y);
    ((__half2*)p)[1] = __floats2half2_rn(v.z, v.w);
}
__device__ __forceinline__ float4 loadh4(const __half* p){
    __half2 a = ((const __half2*)p)[0], b = ((const __half2*)p)[1];
    float2 fa=__half22float2(a), fb=__half22float2(b);
    return make_float4(fa.x,fa.y,fb.x,fb.y);
}

// ======================= MMA plumbing =======================================
__device__ __forceinline__ void cp16(unsigned saddr, const void* g){
    asm volatile("cp.async.cg.shared.global [%0], [%1], 16;" :: "r"(saddr), "l"(g));
}
__device__ __forceinline__ void cp_commit(){
    asm volatile("cp.async.commit_group;" ::: "memory");
}
template<int N> __device__ __forceinline__ void cp_wait(){
    asm volatile("cp.async.wait_group %0;" :: "n"(N) : "memory");
}
__device__ __forceinline__ void ldm4(uint32_t* r, unsigned addr){
    asm volatile("ldmatrix.sync.aligned.m8n8.x4.shared.b16 {%0,%1,%2,%3}, [%4];"
        : "=r"(r[0]), "=r"(r[1]), "=r"(r[2]), "=r"(r[3]) : "r"(addr));
}
__device__ __forceinline__ void mma16816h(float* d, const uint32_t* a, uint32_t b0, uint32_t b1){
    asm volatile("mma.sync.aligned.m16n8k16.row.col.f32.f16.f16.f32 "
        "{%0,%1,%2,%3},{%4,%5,%6,%7},{%8,%9},{%0,%1,%2,%3};"
        : "+f"(d[0]), "+f"(d[1]), "+f"(d[2]), "+f"(d[3])
        : "r"(a[0]), "r"(a[1]), "r"(a[2]), "r"(a[3]), "r"(b0), "r"(b1));
}

// ======================= fp16 single-pass GEMM ==============================
// which 0: out_att(fp32) = g_Sf[2048,640] @ BTf^T (nch=10)
// which 1: g_R2f[z] = h2f[z] @ Wf[z]^T
// which 2: g_Pe[z]  3: g_Pr[z]  4: g_R1[z]
#define STG_F16 24576
#define MMF_SMEM (2*STG_F16)

__device__ __forceinline__ void stageF(unsigned sb,
    const __half* A, size_t lda, int mrow0, int Mv,
    const __half* B, size_t ldb, int kcol, int tid)
{
    for (int i=tid;i<512;i+=256){
        int r=i>>3, c=i&7;
        unsigned off = (unsigned)((r*128 + c*16) ^ ((r&7)<<4));
        int ra = mrow0 + r; if (ra >= Mv) ra = Mv-1;
        cp16(sb + off, A + (size_t)ra*lda + kcol + c*8);
    }
    for (int i=tid;i<1024;i+=256){
        int r=i>>3, c=i&7;
        unsigned off = (unsigned)((r*128 + c*16) ^ ((r&7)<<4));
        cp16(sb + 8192 + off, B + (size_t)r*ldb + kcol + c*8);
    }
}

__global__ void __launch_bounds__(256,3) mma_f16(int which, float* __restrict__ Cf)
{
    extern __shared__ char smraw[];
    unsigned sbase;
    asm("{ .reg .u64 t; cvta.to.shared.u64 t, %1; cvt.u32.u64 %0, t; }" : "=r"(sbase) : "l"(smraw));
    int tid=threadIdx.x, wid=tid>>5, lane=tid&31;
    int wm = wid & 1, wn = wid >> 1;
    int ncol0 = blockIdx.x*128, mrow0 = blockIdx.y*64;
    int z = blockIdx.z;

    const __half *A, *B; __half* C=nullptr; int Nv, ldc, nch, Mv; size_t lda, ldb;
    switch (which){
      case 0:
        A = g_Sf; B = g_BTf + (size_t)ncol0*K_PAD;
        Nv=600; ldc=600; nch=10; lda=K_PAD; ldb=K_PAD; Mv=NGROUP; break;
      case 1:
        A = g_h2f + (size_t)z*M_TOTAL*K_PAD2;
        B = g_Wf[z] + (size_t)ncol0*K_PAD2;
        C = g_R2f + (size_t)z*M_TOTAL*400;
        Nv=400; ldc=400; nch=2; lda=K_PAD2; ldb=K_PAD2; Mv=M_TOTAL; break;
      case 2: {
        int e = (z==2)? 1 : 0;
        A = g_Ef[e]; B = g_Wf[3+z] + (size_t)ncol0*K_PAD2; C = g_Pe[z];
        Nv=400; ldc=400; nch=2; lda=K_PAD2; ldb=K_PAD2; Mv=NENT; break; }
      case 3: {
        int e = (z==2)? 1 : 0;
        A = g_Rf2[e]; B = g_Wf[3+z] + (size_t)ncol0*K_PAD2; C = g_Pr[z];
        Nv=400; ldc=400; nch=2; lda=K_PAD2; ldb=K_PAD2; Mv=NRELS; break; }
      default:
        A = g_h1f[z]; B = g_Wf[z] + (size_t)ncol0*K_PAD2; C = g_R1[z];
        Nv=400; ldc=400; nch=2; lda=K_PAD2; ldb=K_PAD2; Mv=NENT; break;
    }

    float acc[2][4][4];
    #pragma unroll
    for (int i=0;i<2;i++)
        #pragma unroll
        for (int j=0;j<4;j++)
            #pragma unroll
            for (int q=0;q<4;q++) acc[i][j][q]=0.f;

    stageF(sbase,           A,lda,mrow0,Mv, B,ldb, 0,  tid); cp_commit();
    stageF(sbase + STG_F16, A,lda,mrow0,Mv, B,ldb, 64, tid); cp_commit();

    int lr  = lane & 15;
    int lhb = (lane >> 4) << 4;

    for (int k=0;k<nch;k++){
        if (k < nch-1) cp_wait<1>(); else cp_wait<0>();
        __syncthreads();
        unsigned st = sbase + (unsigned)(k&1)*STG_F16;
        unsigned sA = st, sB = st+8192;
        #pragma unroll
        for (int kk=0;kk<4;kk++){
            int cb = kk*32 + lhb;
            uint32_t ah[2][4], bb[2][4];
            #pragma unroll
            for (int mt=0;mt<2;mt++){
                int r = wm*32 + mt*16 + lr;
                unsigned off = (unsigned)((r*128 + cb) ^ ((r&7)<<4));
                ldm4(ah[mt], sA + off);
            }
            #pragma unroll
            for (int ng=0;ng<2;ng++){
                int n = wn*32 + ng*16 + lr;
                unsigned off = (unsigned)((n*128 + cb) ^ ((n&7)<<4));
                ldm4(bb[ng], sB + off);
            }
            #pragma unroll
            for (int mt=0;mt<2;mt++){
                #pragma unroll
                for (int nt=0;nt<4;nt++){
                    int ng = nt>>1, s = nt&1;
                    mma16816h(acc[mt][nt], ah[mt], bb[ng][s], bb[ng][s+2]);
                }
            }
        }
        __syncthreads();
        if (k+2 < nch){
            stageF(st, A,lda,mrow0,Mv, B,ldb, (k+2)*64, tid);
            cp_commit();
        }
    }
    #pragma unroll
    for (int mt=0;mt<2;mt++){
        int rbase = mrow0 + wm*32 + mt*16 + (lane>>2);
        #pragma unroll
        for (int nt=0;nt<4;nt++){
            int col = ncol0 + wn*32 + nt*8 + (lane&3)*2;
            if (col < Nv){
                if (which==0){
                    if (rbase < Mv)
                        *(float2*)(Cf + (size_t)rbase*ldc + col)     = make_float2(acc[mt][nt][0], acc[mt][nt][1]);
                    if (rbase+8 < Mv)
                        *(float2*)(Cf + (size_t)(rbase+8)*ldc + col) = make_float2(acc[mt][nt][2], acc[mt][nt][3]);
                } else {
                    if (rbase < Mv)
                        *(__half2*)(C + (size_t)rbase*ldc + col)     = __floats2half2_rn(acc[mt][nt][0], acc[mt][nt][1]);
                    if (rbase+8 < Mv)
                        *(__half2*)(C + (size_t)(rbase+8)*ldc + col) = __floats2half2_rn(acc[mt][nt][2], acc[mt][nt][3]);
                }
            }
        }
    }
}

// ---------------------------------------------------------------------------
// conversions
// ---------------------------------------------------------------------------
__global__ void convB_kernel(const float* __restrict__ W1)
{
    int i = blockIdx.x*256 + threadIdx.x;
    if (i >= 600*600) return;
    int n = i / 600, k = i - n*600;
    g_BTf[(size_t)n*K_PAD + k] = __float2half(W1[(size_t)k*600 + n]);
}
// v1 = W1 @ a1[0:600], v2 = W1 @ a1[600:1200]
__global__ void v12_kernel(const float* __restrict__ W1, const float* __restrict__ a1)
{
    int k = blockIdx.x;           // 600 blocks, 64 threads (2 warps)
    int w = threadIdx.x >> 5, lane = threadIdx.x & 31;
    const float* av = a1 + w*600;
    const float* row = W1 + (size_t)k*600;
    float s = 0.f;
    for (int n=lane;n<600;n+=32) s += row[n]*av[n];
    #pragma unroll
    for (int o=16;o;o>>=1) s += __shfl_xor_sync(0xffffffffu, s, o);
    if (lane==0){
        if (w==0) g_v1[k]=s; else g_v2[k]=s;
    }
}
__global__ void convW6_kernel(const float* __restrict__ Whf, const float* __restrict__ Whb,
                              const float* __restrict__ Whp, const float* __restrict__ Wif,
                              const float* __restrict__ Wib, const float* __restrict__ Wip)
{
    int i = blockIdx.x*256 + threadIdx.x;
    if (i >= 6*400*100) return;
    int m = i / 40000; int rem = i - m*40000;
    int n = rem/100, k = rem - n*100;
    const float* W;
    switch(m){ case 0:W=Whf;break; case 1:W=Whb;break; case 2:W=Whp;break;
               case 3:W=Wif;break; case 4:W=Wib;break; default:W=Wip;break; }
    g_Wf[m][n*K_PAD2 + k] = __float2half(W[n*100+k]);
}
__global__ void convE_kernel(const float* __restrict__ ent, const float* __restrict__ ent1,
                             const float* __restrict__ rel, const float* __restrict__ rel1)
{
    int i = blockIdx.x*256 + threadIdx.x;
    if (i < 2*NENT*100){
        int e = i / (NENT*100); int rem = i - e*(NENT*100);
        int r = rem/100, k = rem - r*100;
        const float* src = e ? ent1 : ent;
        g_Ef[e][(size_t)r*K_PAD2+k] = __float2half(src[(size_t)r*100+k]);
    } else {
        int j = i - 2*NENT*100;
        if (j >= 2*NRELS*100) return;
        int e = j / (NRELS*100); int rem = j - e*(NRELS*100);
        int r = rem/100, k = rem - r*100;
        const float* src = e ? rel1 : rel;
        g_Rf2[e][(size_t)r*K_PAD2+k] = __float2half(src[(size_t)r*100+k]);
    }
}

// ---------------------------------------------------------------------------
__global__ void step1_kernel(const float* __restrict__ b_f,
                             const float* __restrict__ b_b,
                             const float* __restrict__ b_p)
{
    int idx = blockIdx.x*256 + threadIdx.x;
    if (idx >= 3*NENT*100) return;
    int l   = idx / (NENT*100);
    int rem = idx - l*(NENT*100);
    int e = rem/100, j = rem - e*100;
    const __half* P = g_Pe[l] + (size_t)e*400;
    const float* b = (l==0)? b_f : (l==1)? b_b : b_p;
    float iv = __half2float(P[j])     + b[j];
    float gv = __half2float(P[200+j]) + b[200+j];
    float ov = __half2float(P[300+j]) + b[300+j];
    float c1 = sigmoid_fast(iv) * tanh_fast(gv);
    float h1 = sigmoid_fast(ov) * tanh_fast(c1);
    g_h1c1[l][(size_t)e*200 + j]       = h1;
    g_h1c1[l][(size_t)e*200 + 100 + j] = c1;
    g_h1f[l][(size_t)e*K_PAD2 + j] = __float2half(h1);
}

// ---------------------------------------------------------------------------
__global__ void __launch_bounds__(256) step12_kernel(
    const int* __restrict__ bh, const int* __restrict__ br, const int* __restrict__ bt,
    const float* __restrict__ b_f, const float* __restrict__ b_b, const float* __restrict__ b_p)
{
    __shared__ int ifr[64], ir[64];
    int tid=threadIdx.x; int row0=blockIdx.x*64;
    int l = blockIdx.y;
    if (tid<64)        ifr[tid]    = (l==1)? bt[row0+tid] : bh[row0+tid];
    else if (tid<128)  ir[tid-64]  = br[row0+tid-64];
    __syncthreads();
    const __half* Pr = g_Pr[l];
    const __half* R1 = g_R1[l];
    const float*  HC = g_h1c1[l];
    const float* bias= (l==0)?b_f:(l==1)?b_b:b_p;
    for (int t=tid;t<1600;t+=256){
        int row=t/25, q=t-row*25; int j=q*4;
        int fi = ifr[row];
        size_t grow=(size_t)(row0+row);
        bool emit_out = ((grow % 80u)==0u) && (l<2);
        float4 h1v = *(const float4*)&HC[(size_t)fi*200 + j];
        float4 c1v = *(const float4*)&HC[(size_t)fi*200 + 100 + j];
        if (l==0){
            if (emit_out) *(float4*)&g_out[grow*600 + j] = h1v;
            storeh4(h1v, &g_Af[grow*K_PAD + j]);
        } else if (l==1){
            if (emit_out) *(float4*)&g_out[grow*600 + 500 + j] = h1v;
            storeh4(h1v, &g_Af[grow*K_PAD + 500 + j]);
        }
        const __half* pr = Pr + (size_t)ir[row]*400;
        const __half* r1 = R1 + (size_t)fi*400;
        float4 pi = loadh4(pr+j),      riv = loadh4(r1+j);
        float4 pf = loadh4(pr+100+j),  rf  = loadh4(r1+100+j);
        float4 pg = loadh4(pr+200+j),  rg  = loadh4(r1+200+j);
        float4 po = loadh4(pr+300+j),  ro  = loadh4(r1+300+j);
        float4 bi = *(const float4*)&bias[j],    bf4= *(const float4*)&bias[100+j];
        float4 bg = *(const float4*)&bias[200+j],bo = *(const float4*)&bias[300+j];
        float4 c2v, h2v;
        {
            float c,h;
            c = sigmoid_fast(pf.x+rf.x+bf4.x)*c1v.x + sigmoid_fast(pi.x+riv.x+bi.x)*tanh_fast(pg.x+rg.x+bg.x);
            h = sigmoid_fast(po.x+ro.x+bo.x)*tanh_fast(c); c2v.x=c; h2v.x=h;
            c = sigmoid_fast(pf.y+rf.y+bf4.y)*c1v.y + sigmoid_fast(pi.y+riv.y+bi.y)*tanh_fast(pg.y+rg.y+bg.y);
            h = sigmoid_fast(po.y+ro.y+bo.y)*tanh_fast(c); c2v.y=c; h2v.y=h;
            c = sigmoid_fast(pf.z+rf.z+bf4.z)*c1v.z + sigmoid_fast(pi.z+riv.z+bi.z)*tanh_fast(pg.z+rg.z+bg.z);
            h = sigmoid_fast(po.z+ro.z+bo.z)*tanh_fast(c); c2v.z=c; h2v.z=h;
            c = sigmoid_fast(pf.w+rf.w+bf4.w)*c1v.w + sigmoid_fast(pi.w+riv.w+bi.w)*tanh_fast(pg.w+rg.w+bg.w);
            h = sigmoid_fast(po.w+ro.w+bo.w)*tanh_fast(c); c2v.w=c; h2v.w=h;
        }
        storeh4(h2v, &g_h2f[(size_t)l*M_TOTAL*K_PAD2 + grow*K_PAD2 + j]);
        *(float4*)&g_c2[(size_t)l*M_TOTAL*100 + grow*100 + j] = c2v;
        if (l==0){
            if (emit_out) *(float4*)&g_out[grow*600 + 200 + j] = h2v;
            storeh4(h2v, &g_Af[grow*K_PAD + 200 + j]);
        } else if (l==1){
            if (emit_out) *(float4*)&g_out[grow*600 + 300 + j] = h2v;
            storeh4(h2v, &g_Af[grow*K_PAD + 300 + j]);
        }
    }
}

// ---------------------------------------------------------------------------
__global__ void __launch_bounds__(256) step3_kernel(
    const int* __restrict__ bh, const int* __restrict__ bt,
    const float* __restrict__ b_f, const float* __restrict__ b_b, const float* __restrict__ b_p)
{
    __shared__ int ila[64];
    int tid=threadIdx.x; int row0=blockIdx.x*64;
    int l = blockIdx.y;
    if (tid<64) ila[tid] = (l==1)? bh[row0+tid] : bt[row0+tid];
    __syncthreads();
    const __half* Pe = g_Pe[l];
    const __half* R2 = g_R2f + (size_t)l*M_TOTAL*400;
    const float*  C2 = g_c2 + (size_t)l*M_TOTAL*100;
    const float* bias= (l==0)?b_f:(l==1)?b_b:b_p;
    for (int t=tid;t<1600;t+=256){
        int row=t/25, q=t-row*25; int j=q*4;
        int li = ila[row];
        size_t grow=(size_t)(row0+row);
        const __half* pe = Pe + (size_t)li*400;
        const __half* r2 = R2 + grow*400;
        float4 pi = loadh4(pe+j),      riv = loadh4(r2+j);
        float4 pf = loadh4(pe+100+j),  rf  = loadh4(r2+100+j);
        float4 pg = loadh4(pe+200+j),  rg  = loadh4(r2+200+j);
        float4 po = loadh4(pe+300+j),  ro  = loadh4(r2+300+j);
        float4 bi = *(const float4*)&bias[j],    bf4= *(const float4*)&bias[100+j];
        float4 bg = *(const float4*)&bias[200+j],bo = *(const float4*)&bias[300+j];
        float4 c2v = *(const float4*)&C2[grow*100 + j];
        float4 h3v;
        {
            float c;
            c = sigmoid_fast(pf.x+rf.x+bf4.x)*c2v.x + sigmoid_fast(pi.x+riv.x+bi.x)*tanh_fast(pg.x+rg.x+bg.x);
            h3v.x = sigmoid_fast(po.x+ro.x+bo.x)*tanh_fast(c);
            c = sigmoid_fast(pf.y+rf.y+bf4.y)*c2v.y + sigmoid_fast(pi.y+riv.y+bi.y)*tanh_fast(pg.y+rg.y+bg.y);
            h3v.y = sigmoid_fast(po.y+ro.y+bo.y)*tanh_fast(c);
            c = sigmoid_fast(pf.z+rf.z+bf4.z)*c2v.z + sigmoid_fast(pi.z+riv.z+bi.z)*tanh_fast(pg.z+rg.z+bg.z);
            h3v.z = sigmoid_fast(po.z+ro.z+bo.z)*tanh_fast(c);
            c = sigmoid_fast(pf.w+rf.w+bf4.w)*c2v.w + sigmoid_fast(pi.w+riv.w+bi.w)*tanh_fast(pg.w+rg.w+bg.w);
            h3v.w = sigmoid_fast(po.w+ro.w+bo.w)*tanh_fast(c);
        }
        bool emit_out = ((grow % 80u)==0u);
        if (l==0){
            if (emit_out) *(float4*)&g_out[grow*600 + 400 + j] = h3v;
            storeh4(h3v, &g_Af[grow*K_PAD + 400 + j]);
        } else if (l==1){
            if (emit_out) *(float4*)&g_out[grow*600 + 100 + j] = h3v;
            storeh4(h3v, &g_Af[grow*K_PAD + 100 + j]);
        } else {
            *(float4*)&g_op[grow*100 + j] = h3v;
        }
    }
}

// ---------------------------------------------------------------------------
// GAT1 scores + weighted sum in out-space: g_Sf[b] = att @ out_group (fp16)
// ---------------------------------------------------------------------------
__global__ void __launch_bounds__(256,2) gat1_scores(float* __restrict__ out2)
{
    __shared__ __align__(16) float v1s[600];
    __shared__ __align__(16) float v2s[600];
    __shared__ float ebuf[41];
    __shared__ float att[40];
    __shared__ float red[2];
    int b=blockIdx.x, tid=threadIdx.x, warp=tid>>5, lane=tid&31;
    for (int i=tid;i<600;i+=256) v1s[i]=g_v1[i];
    for (int i=tid;i<600;i+=256) v2s[i]=g_v2[i];
    __syncthreads();
    const __half* base = g_Af + (size_t)b*40*K_PAD;
    for (int t=warp;t<41;t+=8){
        const __half* rowp = (t<40)? base + (size_t)t*K_PAD : base;
        const float* vv    = (t<40)? v1s : v2s;
        float s=0.f;
        for (int kk=lane;kk<75;kk+=32){
            uint4 raw = *(const uint4*)(rowp + kk*8);
            __half2* hv = (__half2*)&raw;
            const float* ap = vv + kk*8;
            float2 f0=__half22float2(hv[0]), f1=__half22float2(hv[1]);
            float2 f2=__half22float2(hv[2]), f3=__half22float2(hv[3]);
            s += f0.x*ap[0]+f0.y*ap[1]+f1.x*ap[2]+f1.y*ap[3]
               + f2.x*ap[4]+f2.y*ap[5]+f3.x*ap[6]+f3.y*ap[7];
        }
        #pragma unroll
        for (int o=16;o;o>>=1) s += __shfl_xor_sync(0xffffffffu, s, o);
        if (lane==0) ebuf[t]=s;
    }
    __syncthreads();
    if (tid<40){
        float x = ebuf[tid] + ebuf[40];
        ebuf[tid] = (x>0.f)? x : 0.2f*x;
    }
    __syncthreads();
    if (tid<32){
        float v = ebuf[tid];
        if (tid<8) v = fmaxf(v, ebuf[tid+32]);
        #pragma unroll
        for (int o=16;o;o>>=1) v = fmaxf(v, __shfl_xor_sync(0xffffffffu, v, o));
        if (tid==0) red[0]=v;
    }
    __syncthreads();
    if (tid<40) att[tid]=__expf(ebuf[tid]-red[0]);
    __syncthreads();
    if (tid<32){
        float v = att[tid] + ((tid<8)? att[tid+32] : 0.f);
        #pragma unroll
        for (int o=16;o;o>>=1) v += __shfl_xor_sync(0xffffffffu, v, o);
        if (tid==0) red[1]=1.f/v;
    }
    __syncthreads();
    if (tid<40) att[tid]=fmaxf(att[tid]*red[1]-0.001f, 0.f);
    __syncthreads();
    __half2* srow = (__half2*)(g_Sf + (size_t)b*K_PAD);
    for (int f2=tid; f2<300; f2+=256){
        float ax=0.f, ay=0.f;
        const __half2* col = (const __half2*)base + f2;
        #pragma unroll 8
        for (int n=0;n<40;n++){
            float2 v = __half22float2(col[(size_t)n*320]);
            ax += att[n]*v.x; ay += att[n]*v.y;
        }
        srow[f2] = __floats2half2_rn(ax, ay);
    }
    if ((b&1)==0){
        const float* sr = g_out + (size_t)b*40*600;
        float* drow = out2 + (size_t)(b>>1)*600;
        for (int f=tid;f<600;f+=256) drow[f]=sr[f];
    }
}

// ---------------------------------------------------------------------------
#define GAT2_SMEM ((4000 + 10000 + 4000)*4)
__global__ void __launch_bounds__(256,1) gat2_kernel(
    const float* __restrict__ W2, const float* __restrict__ a2,
    float* __restrict__ output_att, float* __restrict__ op2)
{
    extern __shared__ float sm[];
    float* ops = sm;
    float* Ws  = ops + 4000;
    float* hg  = Ws  + 10000;
    __shared__ float a2s[200];
    __shared__ float ebuf[41];
    __shared__ float att[40];
    __shared__ float red[2];
    int b=blockIdx.x, tid=threadIdx.x, warp=tid>>5, lane=tid&31;
    const float* src = g_op + (size_t)b*4000;
    for (int i=tid;i<4000;i+=256)  ops[i]=src[i];
    for (int i=tid;i<10000;i+=256) Ws[i]=W2[i];
    if (tid<200) a2s[tid]=a2[tid];
    __syncthreads();
    for (int i=tid;i<4000;i+=256){
        int n=i/100, o=i-n*100;
        float acc=0.f;
        #pragma unroll 4
        for (int k=0;k<100;k++) acc=fmaf(ops[n*100+k], Ws[k*100+o], acc);
        hg[i]=acc;
    }
    __syncthreads();
    for (int t=warp;t<41;t+=8){
        const float* rowp = (t<40)? hg + t*100 : hg;
        const float* av   = (t<40)? a2s        : a2s+100;
        float s=0.f;
        for (int k=lane;k<100;k+=32) s += rowp[k]*av[k];
        #pragma unroll
        for (int o=16;o;o>>=1) s += __shfl_xor_sync(0xffffffffu, s, o);
        if (lane==0) ebuf[t]=s;
    }
    __syncthreads();
    if (tid<40){
        float x = ebuf[tid] + ebuf[40];
        ebuf[tid] = (x>0.f)? x : 0.2f*x;
    }
    __syncthreads();
    if (tid<32){
        float v = ebuf[tid];
        if (tid<8) v = fmaxf(v, ebuf[tid+32]);
        #pragma unroll
        for (int o=16;o;o>>=1) v = fmaxf(v, __shfl_xor_sync(0xffffffffu, v, o));
        if (tid==0) red[0]=v;
    }
    __syncthreads();
    if (tid<40) att[tid]=__expf(ebuf[tid]-red[0]);
    __syncthreads();
    if (tid<32){
        float v = att[tid] + ((tid<8)? att[tid+32] : 0.f);
        #pragma unroll
        for (int o=16;o;o>>=1) v += __shfl_xor_sync(0xffffffffu, v, o);
        if (tid==0) red[1]=1.f/v;
    }
    __syncthreads();
    if (tid<40) att[tid]=fmaxf(att[tid]*red[1]-0.001f, 0.f);
    __syncthreads();
    if (tid<100){
        float acc=0.f;
        #pragma unroll 8
        for (int n=0;n<40;n++) acc += att[n]*hg[n*100+tid];
        output_att[(size_t)b*100+tid]=acc;
    }
    if ((b&1)==0){
        const float* srow = g_op + (size_t)b*40*100;
        float* drow = op2 + (size_t)(b>>1)*100;
        if (tid<100) drow[tid]=srow[tid];
    }
}

// ---------------------------------------------------------------------------
extern "C" void kernel_launch(void* const* d_in, const int* in_sizes, int n_in,
                              void* d_out, int out_size)
{
    const int*   bh    = (const int*)  d_in[0];
    const int*   br    = (const int*)  d_in[1];
    const int*   bt    = (const int*)  d_in[2];
    const float* ent   = (const float*)d_in[3];
    const float* rel   = (const float*)d_in[4];
    const float* ent1  = (const float*)d_in[5];
    const float* rel1  = (const float*)d_in[6];
    const float* Wih_f = (const float*)d_in[7];
    const float* Whh_f = (const float*)d_in[8];
    const float* b_f   = (const float*)d_in[9];
    const float* Wih_b = (const float*)d_in[10];
    const float* Whh_b = (const float*)d_in[11];
    const float* b_b   = (const float*)d_in[12];
    const float* Wih_p = (const float*)d_in[13];
    const float* Whh_p = (const float*)d_in[14];
    const float* b_p   = (const float*)d_in[15];
    const float* W1    = (const float*)d_in[16];
    const float* a1    = (const float*)d_in[17];
    const float* W2    = (const float*)d_in[18];
    const float* a2    = (const float*)d_in[19];

    float* out        = (float*)d_out;
    float* out2       = out;                          // [1024,600]
    float* out_att    = out + 1024*600;               // [2048,600]
    float* op2        = out + 1024*600 + 2048*600;    // [1024,100]
    float* output_att = op2 + 1024*100;               // [2048,100]

    cudaFuncSetAttribute(gat2_kernel, cudaFuncAttributeMaxDynamicSharedMemorySize, GAT2_SMEM);
    cudaFuncSetAttribute(mma_f16,     cudaFuncAttributeMaxDynamicSharedMemorySize, MMF_SMEM);

    convB_kernel<<<(600*600 + 255)/256, 256>>>(W1);
    v12_kernel<<<600, 64>>>(W1, a1);
    convW6_kernel<<<(6*400*100 + 255)/256, 256>>>(Whh_f, Whh_b, Whh_p, Wih_f, Wih_b, Wih_p);
    convE_kernel<<<(2*(NENT+NRELS)*100 + 255)/256, 256>>>(ent, ent1, rel, rel1);

    dim3 pe(4, NENT_P/64, 3);
    mma_f16<<<pe, 256, MMF_SMEM>>>(2, nullptr);
    dim3 pr(4, 4, 3);
    mma_f16<<<pr, 256, MMF_SMEM>>>(3, nullptr);

    step1_kernel<<<(3*NENT*100 + 255)/256, 256>>>(b_f, b_b, b_p);

    mma_f16<<<pe, 256, MMF_SMEM>>>(4, nullptr);

    dim3 sg(M_TOTAL/64, 3);
    step12_kernel<<<sg, 256>>>(bh, br, bt, b_f, b_b, b_p);

    dim3 rg(4, M_TOTAL/64, 3);
    mma_f16<<<rg, 256, MMF_SMEM>>>(1, nullptr);

    step3_kernel<<<sg, 256>>>(bh, bt, b_f, b_b, b_p);

    gat1_scores<<<NGROUP, 256>>>(out2);

    dim3 og(5, NGROUP/64, 1);
    mma_f16<<<og, 256, MMF_SMEM>>>(0, out_att);

    gat2_kernel<<<NGROUP, 256, GAT2_SMEM>>>(W2, a2, output_att, op2);

    (void)in_sizes; (void)n_in; (void)out_size;
}

// round 17
// speedup vs baseline: 1.6993x; 1.3204x over previous
#include <cuda_runtime.h>
#include <cuda_fp16.h>
#include <math.h>
#include <cstdint>

#define M_TOTAL 81920
#define NGROUP  2048
#define NENT    14541
#define NRELS   237
#define NENT_P  14592
#define K_PAD   640
#define K_PAD2  128

// ---------------- scratch (device globals) ----------------------------------
__device__ __half g_Pe[3][NENT*400];        // fp16 gate tables
__device__ __half g_Pr[3][NRELS*400];
__device__ __half g_R1[3][NENT*400];
__device__ float  g_h1c1[3][NENT*200];
__device__ float  g_c2[(size_t)3*M_TOTAL*100];
__device__ __align__(16) __half g_R2f[(size_t)3*M_TOTAL*400];
__device__ float  g_out[(size_t)M_TOTAL*600];
__device__ float  g_op [(size_t)M_TOTAL*100];
// fp16 GEMM operands (pads stay zero)
__device__ __align__(16) __half g_Af[(size_t)M_TOTAL*K_PAD];
__device__ __align__(16) __half g_BTf[640*K_PAD];
__device__ __align__(16) __half g_h2f[(size_t)3*M_TOTAL*K_PAD2];
__device__ __align__(16) __half g_Wf[6][512*K_PAD2];   // 0..2 Whh, 3..5 Wih
__device__ __align__(16) __half g_Ef[2][NENT_P*K_PAD2];
__device__ __align__(16) __half g_Rf2[2][256*K_PAD2];
__device__ __align__(16) __half g_h1f[3][NENT_P*K_PAD2];
// GAT factored pieces
__device__ float g_v1[600];
__device__ float g_v2[600];
__device__ float g_v3[100];
__device__ float g_v4[100];
__device__ __align__(16) __half g_Sf[(size_t)NGROUP*K_PAD];    // pads zero
__device__ __align__(16) __half g_S2f[(size_t)NGROUP*K_PAD2];  // pads zero
__device__ __align__(16) __half g_W2Tf[128*K_PAD2];            // pads zero

__device__ __forceinline__ float tanh_fast(float x){
    float y;
    asm("tanh.approx.f32 %0, %1;" : "=f"(y) : "f"(x));
    return y;
}
__device__ __forceinline__ float sigmoid_fast(float x){
    return fmaf(tanh_fast(0.5f*x), 0.5f, 0.5f);
}
__device__ __forceinline__ void storeh4(float4 v, __half* p){
    ((__half2*)p)[0] = __floats2half2_rn(v.x, v.y);
    ((__half2*)p)[1] = __floats2half2_rn(v.z, v.w);
}
__device__ __forceinline__ float4 loadh4(const __half* p){
    __half2 a = ((const __half2*)p)[0], b = ((const __half2*)p)[1];
    float2 fa=__half22float2(a), fb=__half22float2(b);
    return make_float4(fa.x,fa.y,fb.x,fb.y);
}

// ======================= MMA plumbing =======================================
__device__ __forceinline__ void cp16(unsigned saddr, const void* g){
    asm volatile("cp.async.cg.shared.global [%0], [%1], 16;" :: "r"(saddr), "l"(g));
}
__device__ __forceinline__ void cp_commit(){
    asm volatile("cp.async.commit_group;" ::: "memory");
}
template<int N> __device__ __forceinline__ void cp_wait(){
    asm volatile("cp.async.wait_group %0;" :: "n"(N) : "memory");
}
__device__ __forceinline__ void ldm4(uint32_t* r, unsigned addr){
    asm volatile("ldmatrix.sync.aligned.m8n8.x4.shared.b16 {%0,%1,%2,%3}, [%4];"
        : "=r"(r[0]), "=r"(r[1]), "=r"(r[2]), "=r"(r[3]) : "r"(addr));
}
__device__ __forceinline__ void mma16816h(float* d, const uint32_t* a, uint32_t b0, uint32_t b1){
    asm volatile("mma.sync.aligned.m16n8k16.row.col.f32.f16.f16.f32 "
        "{%0,%1,%2,%3},{%4,%5,%6,%7},{%8,%9},{%0,%1,%2,%3};"
        : "+f"(d[0]), "+f"(d[1]), "+f"(d[2]), "+f"(d[3])
        : "r"(a[0]), "r"(a[1]), "r"(a[2]), "r"(a[3]), "r"(b0), "r"(b1));
}

// ======================= fp16 single-pass GEMM ==============================
// which 0: out_att(fp32) = g_Sf[2048,640] @ BTf^T (nch=10)
// which 1: g_R2f[z] = h2f[z] @ Wf[z]^T
// which 2: g_Pe[z]  3: g_Pr[z]  4: g_R1[z]
// which 5: output_att(fp32) = g_S2f[2048,128] @ W2T^T
#define STG_F16 24576
#define MMF_SMEM (2*STG_F16)

__device__ __forceinline__ void stageF(unsigned sb,
    const __half* A, size_t lda, int mrow0, int Mv,
    const __half* B, size_t ldb, int kcol, int tid)
{
    for (int i=tid;i<512;i+=256){
        int r=i>>3, c=i&7;
        unsigned off = (unsigned)((r*128 + c*16) ^ ((r&7)<<4));
        int ra = mrow0 + r; if (ra >= Mv) ra = Mv-1;
        cp16(sb + off, A + (size_t)ra*lda + kcol + c*8);
    }
    for (int i=tid;i<1024;i+=256){
        int r=i>>3, c=i&7;
        unsigned off = (unsigned)((r*128 + c*16) ^ ((r&7)<<4));
        cp16(sb + 8192 + off, B + (size_t)r*ldb + kcol + c*8);
    }
}

__global__ void __launch_bounds__(256,3) mma_f16(int which, float* __restrict__ Cf)
{
    extern __shared__ char smraw[];
    unsigned sbase;
    asm("{ .reg .u64 t; cvta.to.shared.u64 t, %1; cvt.u32.u64 %0, t; }" : "=r"(sbase) : "l"(smraw));
    int tid=threadIdx.x, wid=tid>>5, lane=tid&31;
    int wm = wid & 1, wn = wid >> 1;
    int ncol0 = blockIdx.x*128, mrow0 = blockIdx.y*64;
    int z = blockIdx.z;

    const __half *A, *B; __half* C=nullptr; int Nv, ldc, nch, Mv; size_t lda, ldb;
    bool f32out = (which==0 || which==5);
    switch (which){
      case 0:
        A = g_Sf; B = g_BTf + (size_t)ncol0*K_PAD;
        Nv=600; ldc=600; nch=10; lda=K_PAD; ldb=K_PAD; Mv=NGROUP; break;
      case 1:
        A = g_h2f + (size_t)z*M_TOTAL*K_PAD2;
        B = g_Wf[z] + (size_t)ncol0*K_PAD2;
        C = g_R2f + (size_t)z*M_TOTAL*400;
        Nv=400; ldc=400; nch=2; lda=K_PAD2; ldb=K_PAD2; Mv=M_TOTAL; break;
      case 2: {
        int e = (z==2)? 1 : 0;
        A = g_Ef[e]; B = g_Wf[3+z] + (size_t)ncol0*K_PAD2; C = g_Pe[z];
        Nv=400; ldc=400; nch=2; lda=K_PAD2; ldb=K_PAD2; Mv=NENT; break; }
      case 3: {
        int e = (z==2)? 1 : 0;
        A = g_Rf2[e]; B = g_Wf[3+z] + (size_t)ncol0*K_PAD2; C = g_Pr[z];
        Nv=400; ldc=400; nch=2; lda=K_PAD2; ldb=K_PAD2; Mv=NRELS; break; }
      case 5:
        A = g_S2f; B = g_W2Tf + (size_t)ncol0*K_PAD2;
        Nv=100; ldc=100; nch=2; lda=K_PAD2; ldb=K_PAD2; Mv=NGROUP; break;
      default:
        A = g_h1f[z]; B = g_Wf[z] + (size_t)ncol0*K_PAD2; C = g_R1[z];
        Nv=400; ldc=400; nch=2; lda=K_PAD2; ldb=K_PAD2; Mv=NENT; break;
    }

    float acc[2][4][4];
    #pragma unroll
    for (int i=0;i<2;i++)
        #pragma unroll
        for (int j=0;j<4;j++)
            #pragma unroll
            for (int q=0;q<4;q++) acc[i][j][q]=0.f;

    stageF(sbase,           A,lda,mrow0,Mv, B,ldb, 0,  tid); cp_commit();
    stageF(sbase + STG_F16, A,lda,mrow0,Mv, B,ldb, 64, tid); cp_commit();

    int lr  = lane & 15;
    int lhb = (lane >> 4) << 4;

    for (int k=0;k<nch;k++){
        if (k < nch-1) cp_wait<1>(); else cp_wait<0>();
        __syncthreads();
        unsigned st = sbase + (unsigned)(k&1)*STG_F16;
        unsigned sA = st, sB = st+8192;
        #pragma unroll
        for (int kk=0;kk<4;kk++){
            int cb = kk*32 + lhb;
            uint32_t ah[2][4], bb[2][4];
            #pragma unroll
            for (int mt=0;mt<2;mt++){
                int r = wm*32 + mt*16 + lr;
                unsigned off = (unsigned)((r*128 + cb) ^ ((r&7)<<4));
                ldm4(ah[mt], sA + off);
            }
            #pragma unroll
            for (int ng=0;ng<2;ng++){
                int n = wn*32 + ng*16 + lr;
                unsigned off = (unsigned)((n*128 + cb) ^ ((n&7)<<4));
                ldm4(bb[ng], sB + off);
            }
            #pragma unroll
            for (int mt=0;mt<2;mt++){
                #pragma unroll
                for (int nt=0;nt<4;nt++){
                    int ng = nt>>1, s = nt&1;
                    mma16816h(acc[mt][nt], ah[mt], bb[ng][s], bb[ng][s+2]);
                }
            }
        }
        __syncthreads();
        if (k+2 < nch){
            stageF(st, A,lda,mrow0,Mv, B,ldb, (k+2)*64, tid);
            cp_commit();
        }
    }
    #pragma unroll
    for (int mt=0;mt<2;mt++){
        int rbase = mrow0 + wm*32 + mt*16 + (lane>>2);
        #pragma unroll
        for (int nt=0;nt<4;nt++){
            int col = ncol0 + wn*32 + nt*8 + (lane&3)*2;
            if (col < Nv){
                if (f32out){
                    if (rbase < Mv)
                        *(float2*)(Cf + (size_t)rbase*ldc + col)     = make_float2(acc[mt][nt][0], acc[mt][nt][1]);
                    if (rbase+8 < Mv)
                        *(float2*)(Cf + (size_t)(rbase+8)*ldc + col) = make_float2(acc[mt][nt][2], acc[mt][nt][3]);
                } else {
                    if (rbase < Mv)
                        *(__half2*)(C + (size_t)rbase*ldc + col)     = __floats2half2_rn(acc[mt][nt][0], acc[mt][nt][1]);
                    if (rbase+8 < Mv)
                        *(__half2*)(C + (size_t)(rbase+8)*ldc + col) = __floats2half2_rn(acc[mt][nt][2], acc[mt][nt][3]);
                }
            }
        }
    }
}

// ---------------------------------------------------------------------------
// conversions
// ---------------------------------------------------------------------------
__global__ void convB_kernel(const float* __restrict__ W1)
{
    int i = blockIdx.x*256 + threadIdx.x;
    if (i >= 600*600) return;
    int n = i / 600, k = i - n*600;
    g_BTf[(size_t)n*K_PAD + k] = __float2half(W1[(size_t)k*600 + n]);
}
// v1 = W1 @ a1[0:600], v2 = W1 @ a1[600:1200]
__global__ void v12_kernel(const float* __restrict__ W1, const float* __restrict__ a1)
{
    int k = blockIdx.x;
    int w = threadIdx.x >> 5, lane = threadIdx.x & 31;
    const float* av = a1 + w*600;
    const float* row = W1 + (size_t)k*600;
    float s = 0.f;
    for (int n=lane;n<600;n+=32) s += row[n]*av[n];
    #pragma unroll
    for (int o=16;o;o>>=1) s += __shfl_xor_sync(0xffffffffu, s, o);
    if (lane==0){
        if (w==0) g_v1[k]=s; else g_v2[k]=s;
    }
}
// v3 = W2 @ a2[0:100], v4 = W2 @ a2[100:200]; also W2^T fp16
__global__ void v34_kernel(const float* __restrict__ W2, const float* __restrict__ a2)
{
    int k = blockIdx.x;   // 100 blocks, 64 threads
    int w = threadIdx.x >> 5, lane = threadIdx.x & 31;
    const float* av = a2 + w*100;
    const float* row = W2 + (size_t)k*100;
    float s = 0.f;
    for (int n=lane;n<100;n+=32) s += row[n]*av[n];
    #pragma unroll
    for (int o=16;o;o>>=1) s += __shfl_xor_sync(0xffffffffu, s, o);
    if (lane==0){
        if (w==0) g_v3[k]=s; else g_v4[k]=s;
    }
    // W2^T: g_W2Tf[o][k] = W2[k][o]
    if (w==0){
        for (int o=lane;o<100;o+=32)
            g_W2Tf[(size_t)o*K_PAD2 + k] = __float2half(row[o]);
    }
}
__global__ void convW6_kernel(const float* __restrict__ Whf, const float* __restrict__ Whb,
                              const float* __restrict__ Whp, const float* __restrict__ Wif,
                              const float* __restrict__ Wib, const float* __restrict__ Wip)
{
    int i = blockIdx.x*256 + threadIdx.x;
    if (i >= 6*400*100) return;
    int m = i / 40000; int rem = i - m*40000;
    int n = rem/100, k = rem - n*100;
    const float* W;
    switch(m){ case 0:W=Whf;break; case 1:W=Whb;break; case 2:W=Whp;break;
               case 3:W=Wif;break; case 4:W=Wib;break; default:W=Wip;break; }
    g_Wf[m][n*K_PAD2 + k] = __float2half(W[n*100+k]);
}
__global__ void convE_kernel(const float* __restrict__ ent, const float* __restrict__ ent1,
                             const float* __restrict__ rel, const float* __restrict__ rel1)
{
    int i = blockIdx.x*256 + threadIdx.x;
    if (i < 2*NENT*100){
        int e = i / (NENT*100); int rem = i - e*(NENT*100);
        int r = rem/100, k = rem - r*100;
        const float* src = e ? ent1 : ent;
        g_Ef[e][(size_t)r*K_PAD2+k] = __float2half(src[(size_t)r*100+k]);
    } else {
        int j = i - 2*NENT*100;
        if (j >= 2*NRELS*100) return;
        int e = j / (NRELS*100); int rem = j - e*(NRELS*100);
        int r = rem/100, k = rem - r*100;
        const float* src = e ? rel1 : rel;
        g_Rf2[e][(size_t)r*K_PAD2+k] = __float2half(src[(size_t)r*100+k]);
    }
}

// ---------------------------------------------------------------------------
__global__ void step1_kernel(const float* __restrict__ b_f,
                             const float* __restrict__ b_b,
                             const float* __restrict__ b_p)
{
    int idx = blockIdx.x*256 + threadIdx.x;
    if (idx >= 3*NENT*100) return;
    int l   = idx / (NENT*100);
    int rem = idx - l*(NENT*100);
    int e = rem/100, j = rem - e*100;
    const __half* P = g_Pe[l] + (size_t)e*400;
    const float* b = (l==0)? b_f : (l==1)? b_b : b_p;
    float iv = __half2float(P[j])     + b[j];
    float gv = __half2float(P[200+j]) + b[200+j];
    float ov = __half2float(P[300+j]) + b[300+j];
    float c1 = sigmoid_fast(iv) * tanh_fast(gv);
    float h1 = sigmoid_fast(ov) * tanh_fast(c1);
    g_h1c1[l][(size_t)e*200 + j]       = h1;
    g_h1c1[l][(size_t)e*200 + 100 + j] = c1;
    g_h1f[l][(size_t)e*K_PAD2 + j] = __float2half(h1);
}

// ---------------------------------------------------------------------------
__global__ void __launch_bounds__(256) step12_kernel(
    const int* __restrict__ bh, const int* __restrict__ br, const int* __restrict__ bt,
    const float* __restrict__ b_f, const float* __restrict__ b_b, const float* __restrict__ b_p)
{
    __shared__ int ifr[64], ir[64];
    int tid=threadIdx.x; int row0=blockIdx.x*64;
    int l = blockIdx.y;
    if (tid<64)        ifr[tid]    = (l==1)? bt[row0+tid] : bh[row0+tid];
    else if (tid<128)  ir[tid-64]  = br[row0+tid-64];
    __syncthreads();
    const __half* Pr = g_Pr[l];
    const __half* R1 = g_R1[l];
    const float*  HC = g_h1c1[l];
    const float* bias= (l==0)?b_f:(l==1)?b_b:b_p;
    for (int t=tid;t<1600;t+=256){
        int row=t/25, q=t-row*25; int j=q*4;
        int fi = ifr[row];
        size_t grow=(size_t)(row0+row);
        bool emit_out = ((grow % 80u)==0u) && (l<2);
        float4 h1v = *(const float4*)&HC[(size_t)fi*200 + j];
        float4 c1v = *(const float4*)&HC[(size_t)fi*200 + 100 + j];
        if (l==0){
            if (emit_out) *(float4*)&g_out[grow*600 + j] = h1v;
            storeh4(h1v, &g_Af[grow*K_PAD + j]);
        } else if (l==1){
            if (emit_out) *(float4*)&g_out[grow*600 + 500 + j] = h1v;
            storeh4(h1v, &g_Af[grow*K_PAD + 500 + j]);
        }
        const __half* pr = Pr + (size_t)ir[row]*400;
        const __half* r1 = R1 + (size_t)fi*400;
        float4 pi = loadh4(pr+j),      riv = loadh4(r1+j);
        float4 pf = loadh4(pr+100+j),  rf  = loadh4(r1+100+j);
        float4 pg = loadh4(pr+200+j),  rg  = loadh4(r1+200+j);
        float4 po = loadh4(pr+300+j),  ro  = loadh4(r1+300+j);
        float4 bi = *(const float4*)&bias[j],    bf4= *(const float4*)&bias[100+j];
        float4 bg = *(const float4*)&bias[200+j],bo = *(const float4*)&bias[300+j];
        float4 c2v, h2v;
        {
            float c,h;
            c = sigmoid_fast(pf.x+rf.x+bf4.x)*c1v.x + sigmoid_fast(pi.x+riv.x+bi.x)*tanh_fast(pg.x+rg.x+bg.x);
            h = sigmoid_fast(po.x+ro.x+bo.x)*tanh_fast(c); c2v.x=c; h2v.x=h;
            c = sigmoid_fast(pf.y+rf.y+bf4.y)*c1v.y + sigmoid_fast(pi.y+riv.y+bi.y)*tanh_fast(pg.y+rg.y+bg.y);
            h = sigmoid_fast(po.y+ro.y+bo.y)*tanh_fast(c); c2v.y=c; h2v.y=h;
            c = sigmoid_fast(pf.z+rf.z+bf4.z)*c1v.z + sigmoid_fast(pi.z+riv.z+bi.z)*tanh_fast(pg.z+rg.z+bg.z);
            h = sigmoid_fast(po.z+ro.z+bo.z)*tanh_fast(c); c2v.z=c; h2v.z=h;
            c = sigmoid_fast(pf.w+rf.w+bf4.w)*c1v.w + sigmoid_fast(pi.w+riv.w+bi.w)*tanh_fast(pg.w+rg.w+bg.w);
            h = sigmoid_fast(po.w+ro.w+bo.w)*tanh_fast(c); c2v.w=c; h2v.w=h;
        }
        storeh4(h2v, &g_h2f[(size_t)l*M_TOTAL*K_PAD2 + grow*K_PAD2 + j]);
        *(float4*)&g_c2[(size_t)l*M_TOTAL*100 + grow*100 + j] = c2v;
        if (l==0){
            if (emit_out) *(float4*)&g_out[grow*600 + 200 + j] = h2v;
            storeh4(h2v, &g_Af[grow*K_PAD + 200 + j]);
        } else if (l==1){
            if (emit_out) *(float4*)&g_out[grow*600 + 300 + j] = h2v;
            storeh4(h2v, &g_Af[grow*K_PAD + 300 + j]);
        }
    }
}

// ---------------------------------------------------------------------------
__global__ void __launch_bounds__(256) step3_kernel(
    const int* __restrict__ bh, const int* __restrict__ bt,
    const float* __restrict__ b_f, const float* __restrict__ b_b, const float* __restrict__ b_p)
{
    __shared__ int ila[64];
    int tid=threadIdx.x; int row0=blockIdx.x*64;
    int l = blockIdx.y;
    if (tid<64) ila[tid] = (l==1)? bh[row0+tid] : bt[row0+tid];
    __syncthreads();
    const __half* Pe = g_Pe[l];
    const __half* R2 = g_R2f + (size_t)l*M_TOTAL*400;
    const float*  C2 = g_c2 + (size_t)l*M_TOTAL*100;
    const float* bias= (l==0)?b_f:(l==1)?b_b:b_p;
    for (int t=tid;t<1600;t+=256){
        int row=t/25, q=t-row*25; int j=q*4;
        int li = ila[row];
        size_t grow=(size_t)(row0+row);
        const __half* pe = Pe + (size_t)li*400;
        const __half* r2 = R2 + grow*400;
        float4 pi = loadh4(pe+j),      riv = loadh4(r2+j);
        float4 pf = loadh4(pe+100+j),  rf  = loadh4(r2+100+j);
        float4 pg = loadh4(pe+200+j),  rg  = loadh4(r2+200+j);
        float4 po = loadh4(pe+300+j),  ro  = loadh4(r2+300+j);
        float4 bi = *(const float4*)&bias[j],    bf4= *(const float4*)&bias[100+j];
        float4 bg = *(const float4*)&bias[200+j],bo = *(const float4*)&bias[300+j];
        float4 c2v = *(const float4*)&C2[grow*100 + j];
        float4 h3v;
        {
            float c;
            c = sigmoid_fast(pf.x+rf.x+bf4.x)*c2v.x + sigmoid_fast(pi.x+riv.x+bi.x)*tanh_fast(pg.x+rg.x+bg.x);
            h3v.x = sigmoid_fast(po.x+ro.x+bo.x)*tanh_fast(c);
            c = sigmoid_fast(pf.y+rf.y+bf4.y)*c2v.y + sigmoid_fast(pi.y+riv.y+bi.y)*tanh_fast(pg.y+rg.y+bg.y);
            h3v.y = sigmoid_fast(po.y+ro.y+bo.y)*tanh_fast(c);
            c = sigmoid_fast(pf.z+rf.z+bf4.z)*c2v.z + sigmoid_fast(pi.z+riv.z+bi.z)*tanh_fast(pg.z+rg.z+bg.z);
            h3v.z = sigmoid_fast(po.z+ro.z+bo.z)*tanh_fast(c);
            c = sigmoid_fast(pf.w+rf.w+bf4.w)*c2v.w + sigmoid_fast(pi.w+riv.w+bi.w)*tanh_fast(pg.w+rg.w+bg.w);
            h3v.w = sigmoid_fast(po.w+ro.w+bo.w)*tanh_fast(c);
        }
        bool emit_out = ((grow % 80u)==0u);
        if (l==0){
            if (emit_out) *(float4*)&g_out[grow*600 + 400 + j] = h3v;
            storeh4(h3v, &g_Af[grow*K_PAD + 400 + j]);
        } else if (l==1){
            if (emit_out) *(float4*)&g_out[grow*600 + 100 + j] = h3v;
            storeh4(h3v, &g_Af[grow*K_PAD + 100 + j]);
        } else {
            *(float4*)&g_op[grow*100 + j] = h3v;
        }
    }
}

// ---------------------------------------------------------------------------
// GAT1 scores + weighted sum: g_Sf[b] = att @ out_group (fp16)
// ---------------------------------------------------------------------------
__global__ void __launch_bounds__(256,2) gat1_scores(float* __restrict__ out2)
{
    __shared__ __align__(16) float v1s[600];
    __shared__ __align__(16) float v2s[600];
    __shared__ float ebuf[41];
    __shared__ float att[40];
    __shared__ float red[2];
    int b=blockIdx.x, tid=threadIdx.x, warp=tid>>5, lane=tid&31;
    for (int i=tid;i<600;i+=256) v1s[i]=g_v1[i];
    for (int i=tid;i<600;i+=256) v2s[i]=g_v2[i];
    __syncthreads();
    const __half* base = g_Af + (size_t)b*40*K_PAD;
    for (int t=warp;t<41;t+=8){
        const __half* rowp = (t<40)? base + (size_t)t*K_PAD : base;
        const float* vv    = (t<40)? v1s : v2s;
        float s=0.f;
        for (int kk=lane;kk<75;kk+=32){
            uint4 raw = *(const uint4*)(rowp + kk*8);
            __half2* hv = (__half2*)&raw;
            const float* ap = vv + kk*8;
            float2 f0=__half22float2(hv[0]), f1=__half22float2(hv[1]);
            float2 f2=__half22float2(hv[2]), f3=__half22float2(hv[3]);
            s += f0.x*ap[0]+f0.y*ap[1]+f1.x*ap[2]+f1.y*ap[3]
               + f2.x*ap[4]+f2.y*ap[5]+f3.x*ap[6]+f3.y*ap[7];
        }
        #pragma unroll
        for (int o=16;o;o>>=1) s += __shfl_xor_sync(0xffffffffu, s, o);
        if (lane==0) ebuf[t]=s;
    }
    __syncthreads();
    if (tid<40){
        float x = ebuf[tid] + ebuf[40];
        ebuf[tid] = (x>0.f)? x : 0.2f*x;
    }
    __syncthreads();
    if (tid<32){
        float v = ebuf[tid];
        if (tid<8) v = fmaxf(v, ebuf[tid+32]);
        #pragma unroll
        for (int o=16;o;o>>=1) v = fmaxf(v, __shfl_xor_sync(0xffffffffu, v, o));
        if (tid==0) red[0]=v;
    }
    __syncthreads();
    if (tid<40) att[tid]=__expf(ebuf[tid]-red[0]);
    __syncthreads();
    if (tid<32){
        float v = att[tid] + ((tid<8)? att[tid+32] : 0.f);
        #pragma unroll
        for (int o=16;o;o>>=1) v += __shfl_xor_sync(0xffffffffu, v, o);
        if (tid==0) red[1]=1.f/v;
    }
    __syncthreads();
    if (tid<40) att[tid]=fmaxf(att[tid]*red[1]-0.001f, 0.f);
    __syncthreads();
    __half2* srow = (__half2*)(g_Sf + (size_t)b*K_PAD);
    for (int f2=tid; f2<300; f2+=256){
        float ax=0.f, ay=0.f;
        const __half2* col = (const __half2*)base + f2;
        #pragma unroll 8
        for (int n=0;n<40;n++){
            float2 v = __half22float2(col[(size_t)n*320]);
            ax += att[n]*v.x; ay += att[n]*v.y;
        }
        srow[f2] = __floats2half2_rn(ax, ay);
    }
    if ((b&1)==0){
        const float* sr = g_out + (size_t)b*40*600;
        float* drow = out2 + (size_t)(b>>1)*600;
        for (int f=tid;f<600;f+=256) drow[f]=sr[f];
    }
}

// ---------------------------------------------------------------------------
// GAT2 scores + weighted sum: g_S2f[b] = att @ op_group (fp16)
// ---------------------------------------------------------------------------
__global__ void __launch_bounds__(256,2) gat2_scores(float* __restrict__ op2)
{
    __shared__ __align__(16) float ops[4000];
    __shared__ float v3s[100], v4s[100];
    __shared__ float ebuf[41];
    __shared__ float att[40];
    __shared__ float red[2];
    int b=blockIdx.x, tid=threadIdx.x, warp=tid>>5, lane=tid&31;
    const float* src = g_op + (size_t)b*4000;
    for (int i=tid;i<4000;i+=256) ops[i]=src[i];
    if (tid<100) v3s[tid]=g_v3[tid];
    else if (tid<200) v4s[tid-100]=g_v4[tid-100];
    __syncthreads();
    for (int t=warp;t<41;t+=8){
        const float* rowp = (t<40)? ops + t*100 : ops;
        const float* vv   = (t<40)? v3s : v4s;
        float s=0.f;
        for (int k=lane;k<100;k+=32) s += rowp[k]*vv[k];
        #pragma unroll
        for (int o=16;o;o>>=1) s += __shfl_xor_sync(0xffffffffu, s, o);
        if (lane==0) ebuf[t]=s;
    }
    __syncthreads();
    if (tid<40){
        float x = ebuf[tid] + ebuf[40];
        ebuf[tid] = (x>0.f)? x : 0.2f*x;
    }
    __syncthreads();
    if (tid<32){
        float v = ebuf[tid];
        if (tid<8) v = fmaxf(v, ebuf[tid+32]);
        #pragma unroll
        for (int o=16;o;o>>=1) v = fmaxf(v, __shfl_xor_sync(0xffffffffu, v, o));
        if (tid==0) red[0]=v;
    }
    __syncthreads();
    if (tid<40) att[tid]=__expf(ebuf[tid]-red[0]);
    __syncthreads();
    if (tid<32){
        float v = att[tid] + ((tid<8)? att[tid+32] : 0.f);
        #pragma unroll
        for (int o=16;o;o>>=1) v += __shfl_xor_sync(0xffffffffu, v, o);
        if (tid==0) red[1]=1.f/v;
    }
    __syncthreads();
    if (tid<40) att[tid]=fmaxf(att[tid]*red[1]-0.001f, 0.f);
    __syncthreads();
    if (tid<100){
        float acc=0.f;
        #pragma unroll 8
        for (int n=0;n<40;n++) acc += att[n]*ops[n*100+tid];
        g_S2f[(size_t)b*K_PAD2 + tid] = __float2half(acc);
    }
    if ((b&1)==0){
        if (tid<100) op2[(size_t)(b>>1)*100 + tid] = ops[tid];
    }
}

// ---------------------------------------------------------------------------
extern "C" void kernel_launch(void* const* d_in, const int* in_sizes, int n_in,
                              void* d_out, int out_size)
{
    const int*   bh    = (const int*)  d_in[0];
    const int*   br    = (const int*)  d_in[1];
    const int*   bt    = (const int*)  d_in[2];
    const float* ent   = (const float*)d_in[3];
    const float* rel   = (const float*)d_in[4];
    const float* ent1  = (const float*)d_in[5];
    const float* rel1  = (const float*)d_in[6];
    const float* Wih_f = (const float*)d_in[7];
    const float* Whh_f = (const float*)d_in[8];
    const float* b_f   = (const float*)d_in[9];
    const float* Wih_b = (const float*)d_in[10];
    const float* Whh_b = (const float*)d_in[11];
    const float* b_b   = (const float*)d_in[12];
    const float* Wih_p = (const float*)d_in[13];
    const float* Whh_p = (const float*)d_in[14];
    const float* b_p   = (const float*)d_in[15];
    const float* W1    = (const float*)d_in[16];
    const float* a1    = (const float*)d_in[17];
    const float* W2    = (const float*)d_in[18];
    const float* a2    = (const float*)d_in[19];

    float* out        = (float*)d_out;
    float* out2       = out;                          // [1024,600]
    float* out_att    = out + 1024*600;               // [2048,600]
    float* op2        = out + 1024*600 + 2048*600;    // [1024,100]
    float* output_att = op2 + 1024*100;               // [2048,100]

    cudaFuncSetAttribute(mma_f16, cudaFuncAttributeMaxDynamicSharedMemorySize, MMF_SMEM);

    convB_kernel<<<(600*600 + 255)/256, 256>>>(W1);
    v12_kernel<<<600, 64>>>(W1, a1);
    v34_kernel<<<100, 64>>>(W2, a2);
    convW6_kernel<<<(6*400*100 + 255)/256, 256>>>(Whh_f, Whh_b, Whh_p, Wih_f, Wih_b, Wih_p);
    convE_kernel<<<(2*(NENT+NRELS)*100 + 255)/256, 256>>>(ent, ent1, rel, rel1);

    dim3 pe(4, NENT_P/64, 3);
    mma_f16<<<pe, 256, MMF_SMEM>>>(2, nullptr);
    dim3 pr(4, 4, 3);
    mma_f16<<<pr, 256, MMF_SMEM>>>(3, nullptr);

    step1_kernel<<<(3*NENT*100 + 255)/256, 256>>>(b_f, b_b, b_p);

    mma_f16<<<pe, 256, MMF_SMEM>>>(4, nullptr);

    dim3 sg(M_TOTAL/64, 3);
    step12_kernel<<<sg, 256>>>(bh, br, bt, b_f, b_b, b_p);

    dim3 rg(4, M_TOTAL/64, 3);
    mma_f16<<<rg, 256, MMF_SMEM>>>(1, nullptr);

    step3_kernel<<<sg, 256>>>(bh, bt, b_f, b_b, b_p);

    gat1_scores<<<NGROUP, 256>>>(out2);
    gat2_scores<<<NGROUP, 256>>>(op2);

    dim3 og(5, NGROUP/64, 1);
    mma_f16<<<og, 256, MMF_SMEM>>>(0, out_att);
    dim3 og2(1, NGROUP/64, 1);
    mma_f16<<<og2, 256, MMF_SMEM>>>(5, output_att);

    (void)in_sizes; (void)n_in; (void)out_size;
}